// round 1
// baseline (speedup 1.0000x reference)
#include <cuda_runtime.h>

#define NN 8192
#define CC 16
#define DD 5
#define TI 256          // threads per block == i's per block
#define TJ 256          // j tile cached in smem
#define JSPLIT 8
#define JCHUNK (NN / JSPLIT)   // 1024

// out = -U  (folds the "- U" term; atomic accumulation adds the W@U part)
__global__ void lg_init_kernel(const float* __restrict__ U, float* __restrict__ out) {
    int idx = blockIdx.x * blockDim.x + threadIdx.x;
    if (idx < NN * CC) out[idx] = -U[idx];
}

__global__ __launch_bounds__(TI) void lg_main_kernel(
    const float* __restrict__ U,
    const float* __restrict__ ref,
    float* __restrict__ out)
{
    __shared__ float  refs[TJ * DD];
    __shared__ float4 us[TJ * (CC / 4)];

    const int tid = threadIdx.x;
    const int i   = blockIdx.x * TI + tid;     // 32 * 256 = 8192 exact
    const int j0  = blockIdx.y * JCHUNK;

    // this thread's reference vector (stays in registers)
    const float r0 = ref[i * DD + 0];
    const float r1 = ref[i * DD + 1];
    const float r2 = ref[i * DD + 2];
    const float r3 = ref[i * DD + 3];
    const float r4 = ref[i * DD + 4];

    float4 a0 = make_float4(0.f, 0.f, 0.f, 0.f);
    float4 a1 = a0, a2 = a0, a3 = a0;

    for (int jt = j0; jt < j0 + JCHUNK; jt += TJ) {
        __syncthreads();
        // cooperative load: ref tile (TJ x 5 floats)
        #pragma unroll
        for (int k = tid; k < TJ * DD; k += TI)
            refs[k] = ref[jt * DD + k];
        // cooperative load: U tile as float4 (TJ x 16 floats = TJ x 4 float4)
        const float4* Ug = (const float4*)(U + jt * CC);
        #pragma unroll
        for (int k = tid; k < TJ * (CC / 4); k += TI)
            us[k] = Ug[k];
        __syncthreads();

        #pragma unroll 4
        for (int jj = 0; jj < TJ; jj++) {
            // squared distance (>=0 by construction, matching max(d2,0))
            float d0 = r0 - refs[jj * DD + 0];
            float d1 = r1 - refs[jj * DD + 1];
            float d2 = r2 - refs[jj * DD + 2];
            float d3 = r3 - refs[jj * DD + 3];
            float d4 = r4 - refs[jj * DD + 4];
            float dd = d0 * d0 + d1 * d1 + d2 * d2 + d3 * d3 + d4 * d4;
            float w  = __expf(-0.5f * dd);   // MUFU.EX2 path

            float4 u0 = us[jj * 4 + 0];
            float4 u1 = us[jj * 4 + 1];
            float4 u2 = us[jj * 4 + 2];
            float4 u3 = us[jj * 4 + 3];
            a0.x += w * u0.x; a0.y += w * u0.y; a0.z += w * u0.z; a0.w += w * u0.w;
            a1.x += w * u1.x; a1.y += w * u1.y; a1.z += w * u1.z; a1.w += w * u1.w;
            a2.x += w * u2.x; a2.y += w * u2.y; a2.z += w * u2.z; a2.w += w * u2.w;
            a3.x += w * u3.x; a3.y += w * u3.y; a3.z += w * u3.z; a3.w += w * u3.w;
        }
    }

    float* o = out + i * CC;
    atomicAdd(o + 0,  a0.x); atomicAdd(o + 1,  a0.y);
    atomicAdd(o + 2,  a0.z); atomicAdd(o + 3,  a0.w);
    atomicAdd(o + 4,  a1.x); atomicAdd(o + 5,  a1.y);
    atomicAdd(o + 6,  a1.z); atomicAdd(o + 7,  a1.w);
    atomicAdd(o + 8,  a2.x); atomicAdd(o + 9,  a2.y);
    atomicAdd(o + 10, a2.z); atomicAdd(o + 11, a2.w);
    atomicAdd(o + 12, a3.x); atomicAdd(o + 13, a3.y);
    atomicAdd(o + 14, a3.z); atomicAdd(o + 15, a3.w);
}

extern "C" void kernel_launch(void* const* d_in, const int* in_sizes, int n_in,
                              void* d_out, int out_size) {
    const float* U   = (const float*)d_in[0];
    const float* ref = (const float*)d_in[1];
    float* out = (float*)d_out;

    lg_init_kernel<<<(NN * CC + 255) / 256, 256>>>(U, out);

    dim3 grid(NN / TI, JSPLIT);
    lg_main_kernel<<<grid, TI>>>(U, ref, out);
}

// round 2
// speedup vs baseline: 1.2889x; 1.2889x over previous
#include <cuda_runtime.h>

#define NN 8192
#define CC 16
#define DD 5
#define TI 128            // threads per block
#define MI 2              // i-rows per thread
#define TJ 256            // j tile in smem
#define JSPLIT 32
#define JCHUNK (NN / JSPLIT)   // 256 == TJ: one tile per CTA

// scratch (no cudaMalloc allowed)
__device__ float g_refS[NN * DD];   // ref scaled by sqrt(log2(e))
__device__ float g_Up[NN * CC];     // E_j * U_j
__device__ float g_E[NN];           // exp(-0.5*||r_j||^2)

// Precompute: E, scaled refs, U' = E*U, and out = -U
__global__ void lg_pre_kernel(const float* __restrict__ U,
                              const float* __restrict__ ref,
                              float* __restrict__ out) {
    const int i = blockIdx.x * blockDim.x + threadIdx.x;
    if (i >= NN) return;
    const float SQRT_LOG2E = 1.2011224087864498f;  // sqrt(log2(e))
    float r[DD], s = 0.f;
#pragma unroll
    for (int k = 0; k < DD; k++) { r[k] = ref[i * DD + k]; s += r[k] * r[k]; }
    float e = __expf(-0.5f * s);
    g_E[i] = e;
#pragma unroll
    for (int k = 0; k < DD; k++) g_refS[i * DD + k] = r[k] * SQRT_LOG2E;
#pragma unroll
    for (int c = 0; c < CC; c++) {
        float u = U[i * CC + c];
        g_Up[i * CC + c] = e * u;
        out[i * CC + c] = -u;
    }
}

__device__ __forceinline__ float ex2f(float x) {
    float y;
    asm("ex2.approx.f32 %0, %1;" : "=f"(y) : "f"(x));
    return y;
}
__device__ __forceinline__ unsigned long long packff(float x) {
    unsigned long long v;
    asm("mov.b64 %0, {%1, %1};" : "=l"(v) : "f"(x));
    return v;
}
__device__ __forceinline__ void fma2(unsigned long long& d,
                                     unsigned long long a,
                                     unsigned long long b) {
    asm("fma.rn.f32x2 %0, %1, %2, %0;" : "+l"(d) : "l"(a), "l"(b));
}
__device__ __forceinline__ void unpack2(unsigned long long v, float& lo, float& hi) {
    asm("mov.b64 {%0, %1}, %2;" : "=f"(lo), "=f"(hi) : "l"(v));
}

__global__ __launch_bounds__(TI) void lg_main_kernel(float* __restrict__ out) {
    __shared__ float srefs[TJ * DD];
    __shared__ ulonglong2 sU[TJ * 2];   // TJ rows x 16 floats = TJ x 2 ulonglong2... (32B) -> actually 4 x 16B

    // NOTE: 16 floats = 64B = 4 ulonglong2 per row
    __shared__ ulonglong2 sU2[TJ * 2];  // second half

    const int tid = threadIdx.x;
    const int i0 = blockIdx.x * (TI * MI) + tid;
    const int i1 = i0 + TI;
    const int j0 = blockIdx.y * JCHUNK;

    // i-side registers
    float a0 = g_refS[i0 * DD + 0], a1 = g_refS[i0 * DD + 1], a2 = g_refS[i0 * DD + 2],
          a3 = g_refS[i0 * DD + 3], a4 = g_refS[i0 * DD + 4];
    float b0 = g_refS[i1 * DD + 0], b1 = g_refS[i1 * DD + 1], b2 = g_refS[i1 * DD + 2],
          b3 = g_refS[i1 * DD + 3], b4 = g_refS[i1 * DD + 4];
    const float eA = g_E[i0];
    const float eB = g_E[i1];

    // cooperative tile loads
#pragma unroll
    for (int k = tid; k < TJ * DD; k += TI) srefs[k] = g_refS[j0 * DD + k];
    {
        const float4* ug = (const float4*)(g_Up + j0 * CC);
        float4* s1 = (float4*)sU;   // rows' first 32B
        float4* s2 = (float4*)sU2;  // rows' second 32B
        // interleave so row jj: sU[jj*2+0..1] = floats 0..7, sU2[jj*2+0..1] = floats 8..15
#pragma unroll
        for (int k = tid; k < TJ; k += TI) {
            s1[k * 2 + 0] = ug[k * 4 + 0];
            s1[k * 2 + 1] = ug[k * 4 + 1];
            s2[k * 2 + 0] = ug[k * 4 + 2];
            s2[k * 2 + 1] = ug[k * 4 + 3];
        }
    }
    __syncthreads();

    unsigned long long acc[16];
#pragma unroll
    for (int q = 0; q < 16; q++) acc[q] = 0ull;

#pragma unroll 4
    for (int jj = 0; jj < TJ; jj++) {
        float q0 = srefs[jj * DD + 0];
        float q1 = srefs[jj * DD + 1];
        float q2 = srefs[jj * DD + 2];
        float q3 = srefs[jj * DD + 3];
        float q4 = srefs[jj * DD + 4];

        float dA = fmaf(a4, q4, fmaf(a3, q3, fmaf(a2, q2, fmaf(a1, q1, a0 * q0))));
        float dB = fmaf(b4, q4, fmaf(b3, q3, fmaf(b2, q2, fmaf(b1, q1, b0 * q0))));
        unsigned long long wA = packff(ex2f(dA));
        unsigned long long wB = packff(ex2f(dB));

        ulonglong2 p0 = sU[jj * 2 + 0];
        ulonglong2 p1 = sU[jj * 2 + 1];
        ulonglong2 p2 = sU2[jj * 2 + 0];
        ulonglong2 p3 = sU2[jj * 2 + 1];

        fma2(acc[0], wA, p0.x); fma2(acc[1], wA, p0.y);
        fma2(acc[2], wA, p1.x); fma2(acc[3], wA, p1.y);
        fma2(acc[4], wA, p2.x); fma2(acc[5], wA, p2.y);
        fma2(acc[6], wA, p3.x); fma2(acc[7], wA, p3.y);
        fma2(acc[8],  wB, p0.x); fma2(acc[9],  wB, p0.y);
        fma2(acc[10], wB, p1.x); fma2(acc[11], wB, p1.y);
        fma2(acc[12], wB, p2.x); fma2(acc[13], wB, p2.y);
        fma2(acc[14], wB, p3.x); fma2(acc[15], wB, p3.y);
    }

    float* oA = out + i0 * CC;
    float* oB = out + i1 * CC;
#pragma unroll
    for (int q = 0; q < 8; q++) {
        float lo, hi;
        unpack2(acc[q], lo, hi);
        atomicAdd(oA + 2 * q + 0, eA * lo);
        atomicAdd(oA + 2 * q + 1, eA * hi);
    }
#pragma unroll
    for (int q = 0; q < 8; q++) {
        float lo, hi;
        unpack2(acc[8 + q], lo, hi);
        atomicAdd(oB + 2 * q + 0, eB * lo);
        atomicAdd(oB + 2 * q + 1, eB * hi);
    }
}

extern "C" void kernel_launch(void* const* d_in, const int* in_sizes, int n_in,
                              void* d_out, int out_size) {
    const float* U   = (const float*)d_in[0];
    const float* ref = (const float*)d_in[1];
    float* out = (float*)d_out;

    lg_pre_kernel<<<(NN + 255) / 256, 256>>>(U, ref, out);

    dim3 grid(NN / (TI * MI), JSPLIT);
    lg_main_kernel<<<grid, TI>>>(out);
}

// round 4
// speedup vs baseline: 3.3206x; 2.5763x over previous
#include <cuda_runtime.h>
#include <cuda_fp16.h>

#define NN 8192
#define CC 16
#define KAUG 40          // padded K (halves) per augmented row: 32 used + 8 pad
#define UPAD 136         // padded U^T row (halves)
#define THREADS 256
#define NTILES 16        // j-tiles of 128 per CTA (grid.y = 4)

// ---------------- device scratch (no cudaMalloc allowed) ----------------
__device__ __align__(16) __half g_Aaug[NN * KAUG];        // [i][40] halves
__device__ __align__(16) __half g_Baug[NN * KAUG];        // [j][40] halves
__device__ __align__(16) __half g_UT[64 * CC * 128];      // [tile][c][j] halves

// ---------------- helpers ----------------
__device__ __forceinline__ unsigned s2u(const void* p) {
    return (unsigned)__cvta_generic_to_shared(p);
}
__device__ __forceinline__ float ex2f(float x) {
    float y; asm("ex2.approx.f32 %0, %1;" : "=f"(y) : "f"(x)); return y;
}
__device__ __forceinline__ unsigned cvt2h(float hi, float lo) {
    unsigned d; asm("cvt.rn.f16x2.f32 %0, %1, %2;" : "=r"(d) : "f"(hi), "f"(lo)); return d;
}
__device__ __forceinline__ void ldsm4(unsigned& r0, unsigned& r1, unsigned& r2, unsigned& r3, unsigned a) {
    asm volatile("ldmatrix.sync.aligned.m8n8.x4.shared.b16 {%0,%1,%2,%3}, [%4];"
                 : "=r"(r0), "=r"(r1), "=r"(r2), "=r"(r3) : "r"(a));
}
__device__ __forceinline__ void mma16816(float* c, unsigned a0, unsigned a1, unsigned a2, unsigned a3,
                                         unsigned b0, unsigned b1) {
    asm volatile("mma.sync.aligned.m16n8k16.row.col.f32.f16.f16.f32 "
                 "{%0,%1,%2,%3}, {%4,%5,%6,%7}, {%8,%9}, {%0,%1,%2,%3};"
                 : "+f"(c[0]), "+f"(c[1]), "+f"(c[2]), "+f"(c[3])
                 : "r"(a0), "r"(a1), "r"(a2), "r"(a3), "r"(b0), "r"(b1));
}
__device__ __forceinline__ void cp16(unsigned saddr, const void* g) {
    asm volatile("cp.async.ca.shared.global [%0], [%1], 16;" :: "r"(saddr), "l"(g));
}
#define CP_COMMIT() asm volatile("cp.async.commit_group;" ::: "memory")

// ---------------- pre-kernel ----------------
__global__ void lg_pre_kernel(const float* __restrict__ U,
                              const float* __restrict__ ref,
                              float* __restrict__ out) {
    const int idx = blockIdx.x * blockDim.x + threadIdx.x;
    const float SC = 1.2011224087864498f;  // sqrt(log2 e)
    if (idx < NN) {
        const int i = idx;
        float rs[5], ss = 0.f;
#pragma unroll
        for (int k = 0; k < 5; k++) { rs[k] = ref[i * 5 + k] * SC; ss += rs[k] * rs[k]; }
        float c = -0.5f * ss;
        unsigned short rh[5], rl[5], chh, cll;
#pragma unroll
        for (int k = 0; k < 5; k++) {
            __half hh = __float2half_rn(rs[k]);
            rh[k] = __half_as_ushort(hh);
            rl[k] = __half_as_ushort(__float2half_rn(rs[k] - __half2float(hh)));
        }
        {
            __half hc = __float2half_rn(c);
            chh = __half_as_ushort(hc);
            cll = __half_as_ushort(__float2half_rn(c - __half2float(hc)));
        }
        const unsigned short ONE = 0x3C00;
        unsigned short A[KAUG], B[KAUG];
#pragma unroll
        for (int k = 0; k < KAUG; k++) { A[k] = 0; B[k] = 0; }
        // A row: k0-7 = [rh,ch,1,0]; k8-15 = [rl,cl,0,0]; k16-23 = [rh,ch,1,0]
#pragma unroll
        for (int k = 0; k < 5; k++) { A[k] = rh[k]; A[8 + k] = rl[k]; A[16 + k] = rh[k]; }
        A[5] = chh; A[6] = ONE; A[13] = cll; A[21] = chh; A[22] = ONE;
        // B row: k0-7 = [rh,1,ch,0]; k8-15 = same; k16-23 = [rl,0,cl,0]
#pragma unroll
        for (int k = 0; k < 5; k++) { B[k] = rh[k]; B[8 + k] = rh[k]; B[16 + k] = rl[k]; }
        B[5] = ONE; B[6] = chh; B[13] = ONE; B[14] = chh; B[22] = cll;
        uint4* gA = (uint4*)(g_Aaug + (size_t)i * KAUG);
        uint4* gB = (uint4*)(g_Baug + (size_t)i * KAUG);
#pragma unroll
        for (int q = 0; q < 5; q++) {
            gA[q] = ((const uint4*)A)[q];
            gB[q] = ((const uint4*)B)[q];
        }
        // out = -U
        const float4* u4 = (const float4*)(U + i * CC);
        float4* o4 = (float4*)(out + i * CC);
#pragma unroll
        for (int q = 0; q < 4; q++) {
            float4 v = u4[q];
            o4[q] = make_float4(-v.x, -v.y, -v.z, -v.w);
        }
    } else if (idx < NN + 64 * CC * 16) {
        // U^T tiles: g_UT[tile][c][128], written 8 j's (one uint4) per thread
        const int id2 = idx - NN;
        const int tile = id2 >> 8;
        const int c = (id2 >> 4) & 15;
        const int q = id2 & 15;
        const int j0 = tile * 128 + q * 8;
        unsigned wv[4];
#pragma unroll
        for (int m = 0; m < 4; m++) {
            unsigned short lo = __half_as_ushort(__float2half_rn(U[(j0 + 2 * m) * CC + c]));
            unsigned short hi = __half_as_ushort(__float2half_rn(U[(j0 + 2 * m + 1) * CC + c]));
            wv[m] = (unsigned)lo | ((unsigned)hi << 16);
        }
        uint4* dst = (uint4*)(g_UT + ((size_t)tile * CC + c) * 128 + q * 8);
        *dst = make_uint4(wv[0], wv[1], wv[2], wv[3]);
    }
}

// ---------------- main kernel ----------------
__global__ __launch_bounds__(THREADS, 2) void lg_main_kernel(float* __restrict__ out) {
    __shared__ __align__(16) __half sA[128 * KAUG];
    __shared__ __align__(16) __half sB[2][128 * KAUG];
    __shared__ __align__(16) __half sU[2][CC * UPAD];

    const int tid = threadIdx.x;
    const int w = tid >> 5;
    const int l = tid & 31;
    const int bx = blockIdx.x;
    const int by = blockIdx.y;

    const unsigned sAb = s2u(sA);
    const unsigned sBb0 = s2u(sB[0]);
    const unsigned sBb1 = s2u(sB[1]);
    const unsigned sUb0 = s2u(sU[0]);
    const unsigned sUb1 = s2u(sU[1]);

    // ---- prologue copies (cp.async) ----
    {
        const char* gA = (const char*)(g_Aaug) + (size_t)bx * 128 * KAUG * 2;
        for (int k = tid; k < 640; k += THREADS) cp16(sAb + k * 16, gA + k * 16);
        const int jt0 = by * NTILES;
        const char* gB = (const char*)(g_Baug) + (size_t)jt0 * 128 * KAUG * 2;
        for (int k = tid; k < 640; k += THREADS) cp16(sBb0 + k * 16, gB + k * 16);
        const char* gU = (const char*)(g_UT) + (size_t)jt0 * CC * 256;
        for (int k = tid; k < 256; k += THREADS) {
            int row = k >> 4, q = k & 15;
            cp16(sUb0 + row * (UPAD * 2) + q * 16, gU + k * 16);
        }
        CP_COMMIT();
        const char* gB1 = (const char*)(g_Baug) + (size_t)(jt0 + 1) * 128 * KAUG * 2;
        for (int k = tid; k < 640; k += THREADS) cp16(sBb1 + k * 16, gB1 + k * 16);
        const char* gU1 = (const char*)(g_UT) + (size_t)(jt0 + 1) * CC * 256;
        for (int k = tid; k < 256; k += THREADS) {
            int row = k >> 4, q = k & 15;
            cp16(sUb1 + row * (UPAD * 2) + q * 16, gU1 + k * 16);
        }
        CP_COMMIT();
    }

    // lane address pieces
    const int lrowB = ((l >> 4) & 1) * 8 + (l & 7);   // B/U tile row selector
    const int lkB   = ((l >> 3) & 1) * 16;            // B/U k-half byte offset
    const int lrowA = ((l >> 3) & 1) * 8 + (l & 7);   // A tile row selector
    const int lkA   = ((l >> 4) & 1) * 16;            // A k-half byte offset

    const unsigned aAddr0 = sAb + (w * 16 + lrowA) * (KAUG * 2) + lkA;          // kstep 0
    const unsigned uAddrB = sUb0 + lrowB * (UPAD * 2) + lkB;                    // per-buffer rebased below

    unsigned aF[2][4];
    float o[2][4];
#pragma unroll
    for (int nb = 0; nb < 2; nb++)
#pragma unroll
        for (int q = 0; q < 4; q++) o[nb][q] = 0.f;

    bool aLoaded = false;

    for (int t = 0; t < NTILES; t++) {
        if (t == NTILES - 1) asm volatile("cp.async.wait_group 0;" ::: "memory");
        else                 asm volatile("cp.async.wait_group 1;" ::: "memory");
        __syncthreads();

        if (!aLoaded) {
            ldsm4(aF[0][0], aF[0][1], aF[0][2], aF[0][3], aAddr0);
            ldsm4(aF[1][0], aF[1][1], aF[1][2], aF[1][3], aAddr0 + 32);
            aLoaded = true;
        }

        const unsigned bBase = (t & 1) ? sBb1 : sBb0;
        const unsigned uBase = (t & 1) ? sUb1 : sUb0;

        // ---- GEMM1: S[16 x 128] = A_aug @ B_aug^T (K=32, two k16 steps) ----
        float s[16][4];
#pragma unroll
        for (int nb = 0; nb < 16; nb++)
#pragma unroll
            for (int q = 0; q < 4; q++) s[nb][q] = 0.f;

#pragma unroll
        for (int k = 0; k < 2; k++) {
#pragma unroll
            for (int p = 0; p < 8; p++) {
                unsigned b0, b1, b2, b3;
                unsigned addr = bBase + (p * 16 + lrowB) * (KAUG * 2) + k * 32 + lkB;
                ldsm4(b0, b1, b2, b3, addr);
                mma16816(s[2 * p],     aF[k][0], aF[k][1], aF[k][2], aF[k][3], b0, b1);
                mma16816(s[2 * p + 1], aF[k][0], aF[k][1], aF[k][2], aF[k][3], b2, b3);
            }
        }

        // ---- exp2 + cvt to fp16 pairs (W fragments == A fragments of GEMM2) ----
        unsigned wf[16][2];
#pragma unroll
        for (int nb = 0; nb < 16; nb++) {
            float e0 = ex2f(s[nb][0]);
            float e1 = ex2f(s[nb][1]);
            float e2 = ex2f(s[nb][2]);
            float e3 = ex2f(s[nb][3]);
            wf[nb][0] = cvt2h(e1, e0);
            wf[nb][1] = cvt2h(e3, e2);
        }

        // ---- GEMM2: O[16 x 16] += W[16 x 128] @ U[128 x 16] ----
#pragma unroll
        for (int kt = 0; kt < 8; kt++) {
            unsigned u0, u1, u2, u3;
            unsigned addr = uBase + lrowB * (UPAD * 2) + kt * 32 + lkB;
            ldsm4(u0, u1, u2, u3, addr);
            mma16816(o[0], wf[2 * kt][0], wf[2 * kt][1], wf[2 * kt + 1][0], wf[2 * kt + 1][1], u0, u1);
            mma16816(o[1], wf[2 * kt][0], wf[2 * kt][1], wf[2 * kt + 1][0], wf[2 * kt + 1][1], u2, u3);
        }

        __syncthreads();

        // ---- prefetch tile t+2 into the buffer just freed ----
        if (t + 2 < NTILES) {
            const int jt = by * NTILES + t + 2;
            const unsigned dB = (t & 1) ? sBb1 : sBb0;
            const unsigned dU = (t & 1) ? sUb1 : sUb0;
            const char* gB = (const char*)(g_Baug) + (size_t)jt * 128 * KAUG * 2;
            for (int k = tid; k < 640; k += THREADS) cp16(dB + k * 16, gB + k * 16);
            const char* gU = (const char*)(g_UT) + (size_t)jt * CC * 256;
            for (int k = tid; k < 256; k += THREADS) {
                int row = k >> 4, q = k & 15;
                cp16(dU + row * (UPAD * 2) + q * 16, gU + k * 16);
            }
            CP_COMMIT();
        } else {
            CP_COMMIT();  // keep group counting consistent
        }
    }

    // ---- epilogue: scatter O fragments ----
    const int g = l >> 2;
    const int tq = l & 3;
    const int i0 = bx * 128 + w * 16 + g;
#pragma unroll
    for (int nb = 0; nb < 2; nb++) {
        const int col = nb * 8 + tq * 2;
        atomicAdd(&out[i0 * CC + col],       o[nb][0]);
        atomicAdd(&out[i0 * CC + col + 1],   o[nb][1]);
        atomicAdd(&out[(i0 + 8) * CC + col],     o[nb][2]);
        atomicAdd(&out[(i0 + 8) * CC + col + 1], o[nb][3]);
    }
}

extern "C" void kernel_launch(void* const* d_in, const int* in_sizes, int n_in,
                              void* d_out, int out_size) {
    const float* U   = (const float*)d_in[0];
    const float* ref = (const float*)d_in[1];
    float* out = (float*)d_out;

    const int preN = NN + 64 * CC * 16;
    lg_pre_kernel<<<(preN + 255) / 256, 256>>>(U, ref, out);

    dim3 grid(NN / 128, 4);
    lg_main_kernel<<<grid, THREADS>>>(out);
}

// round 5
// speedup vs baseline: 4.0654x; 1.2243x over previous
#include <cuda_runtime.h>
#include <cuda_fp16.h>

#define NN 8192
#define CC 16
#define KAUG 40          // padded K (halves) per augmented row: 24 used + pad
#define UPAD 136         // padded U^T row (halves)
#define THREADS 256
#define NTILES 4         // j-tiles of 128 per CTA (grid.y = 16)

// ---------------- device scratch (no cudaMalloc allowed) ----------------
__device__ __align__(16) __half g_Aaug[NN * KAUG];
__device__ __align__(16) __half g_Baug[NN * KAUG];
__device__ __align__(16) __half g_UT[64 * CC * 128];   // [tile][c][j]

// ---------------- helpers ----------------
__device__ __forceinline__ unsigned s2u(const void* p) {
    return (unsigned)__cvta_generic_to_shared(p);
}
__device__ __forceinline__ unsigned cvt2h(float hi, float lo) {
    unsigned d; asm("cvt.rn.f16x2.f32 %0, %1, %2;" : "=r"(d) : "f"(hi), "f"(lo)); return d;
}
__device__ __forceinline__ unsigned ex2h(unsigned x) {
    unsigned y; asm("ex2.approx.f16x2 %0, %1;" : "=r"(y) : "r"(x)); return y;
}
__device__ __forceinline__ void ldsm4(unsigned& r0, unsigned& r1, unsigned& r2, unsigned& r3, unsigned a) {
    asm volatile("ldmatrix.sync.aligned.m8n8.x4.shared.b16 {%0,%1,%2,%3}, [%4];"
                 : "=r"(r0), "=r"(r1), "=r"(r2), "=r"(r3) : "r"(a));
}
__device__ __forceinline__ void mma16816(float* c, unsigned a0, unsigned a1, unsigned a2, unsigned a3,
                                         unsigned b0, unsigned b1) {
    asm volatile("mma.sync.aligned.m16n8k16.row.col.f32.f16.f16.f32 "
                 "{%0,%1,%2,%3}, {%4,%5,%6,%7}, {%8,%9}, {%0,%1,%2,%3};"
                 : "+f"(c[0]), "+f"(c[1]), "+f"(c[2]), "+f"(c[3])
                 : "r"(a0), "r"(a1), "r"(a2), "r"(a3), "r"(b0), "r"(b1));
}
__device__ __forceinline__ void cp16(unsigned saddr, const void* g) {
    asm volatile("cp.async.ca.shared.global [%0], [%1], 16;" :: "r"(saddr), "l"(g));
}
#define CP_COMMIT() asm volatile("cp.async.commit_group;" ::: "memory")

// ---------------- pre-kernel: 32 blocks x 256 threads ----------------
__global__ __launch_bounds__(256) void lg_pre_kernel(const float* __restrict__ U,
                                                     const float* __restrict__ ref,
                                                     float* __restrict__ out) {
    __shared__ __half sUh[256 * 17];   // [j_local][c], padded to 17
    const int b = blockIdx.x;
    const int tid = threadIdx.x;

    // part 1: load U block (256 rows), write out = -U, stage f16 in smem (all coalesced)
#pragma unroll
    for (int k = 0; k < 16; k++) {
        int idx = k * 256 + tid;               // 0..4095 over 256 rows x 16 cols
        float f = U[b * 4096 + idx];
        out[b * 4096 + idx] = -f;
        sUh[(idx >> 4) * 17 + (idx & 15)] = __float2half_rn(f);
    }
    __syncthreads();

    // part 2: transposed U^T tiles (2 tiles per block), coalesced uint writes
    unsigned* gUTu = (unsigned*)g_UT;
#pragma unroll
    for (int k = 0; k < 8; k++) {
        int w = k * 256 + tid;                 // 0..2047 uints
        int tl = w >> 10;                      // tile_local 0..1
        int c  = (w >> 6) & 15;
        int j2 = w & 63;                       // uint index along j (2 j's)
        __half h0 = sUh[(tl * 128 + 2 * j2) * 17 + c];
        __half h1 = sUh[(tl * 128 + 2 * j2 + 1) * 17 + c];
        unsigned v = (unsigned)__half_as_ushort(h0) | ((unsigned)__half_as_ushort(h1) << 16);
        gUTu[((size_t)(b * 2 + tl) * 16 + c) * 64 + j2] = v;
    }

    // part 3: augmented split-fp16 A/B rows
    {
        const int i = b * 256 + tid;
        const float SC = 1.2011224087864498f;  // sqrt(log2 e)
        float rs[5], ss = 0.f;
#pragma unroll
        for (int k = 0; k < 5; k++) { rs[k] = ref[i * 5 + k] * SC; ss += rs[k] * rs[k]; }
        float c = -0.5f * ss;
        unsigned short rh[5], rl[5], chh, cll;
#pragma unroll
        for (int k = 0; k < 5; k++) {
            __half hh = __float2half_rn(rs[k]);
            rh[k] = __half_as_ushort(hh);
            rl[k] = __half_as_ushort(__float2half_rn(rs[k] - __half2float(hh)));
        }
        {
            __half hc = __float2half_rn(c);
            chh = __half_as_ushort(hc);
            cll = __half_as_ushort(__float2half_rn(c - __half2float(hc)));
        }
        const unsigned short ONE = 0x3C00;
        unsigned short A[KAUG], B[KAUG];
#pragma unroll
        for (int k = 0; k < KAUG; k++) { A[k] = 0; B[k] = 0; }
        // A: k0-7=[rh,ch,1,0]  k8-15=[rl,cl,0,0]  k16-23=[rh,ch,1,0]
#pragma unroll
        for (int k = 0; k < 5; k++) { A[k] = rh[k]; A[8 + k] = rl[k]; A[16 + k] = rh[k]; }
        A[5] = chh; A[6] = ONE; A[13] = cll; A[21] = chh; A[22] = ONE;
        // B: k0-7=[rh,1,ch,0]  k8-15=same  k16-23=[rl,0,cl,0]
#pragma unroll
        for (int k = 0; k < 5; k++) { B[k] = rh[k]; B[8 + k] = rh[k]; B[16 + k] = rl[k]; }
        B[5] = ONE; B[6] = chh; B[13] = ONE; B[14] = chh; B[22] = cll;
        uint4* gA = (uint4*)(g_Aaug + (size_t)i * KAUG);
        uint4* gB = (uint4*)(g_Baug + (size_t)i * KAUG);
#pragma unroll
        for (int q = 0; q < 5; q++) {
            gA[q] = ((const uint4*)A)[q];
            gB[q] = ((const uint4*)B)[q];
        }
    }
}

// ---------------- main kernel ----------------
__global__ __launch_bounds__(THREADS, 3) void lg_main_kernel(float* __restrict__ out) {
    __shared__ __align__(16) __half sA[128 * KAUG];
    __shared__ __align__(16) __half sB[2][128 * KAUG];
    __shared__ __align__(16) __half sU[2][CC * UPAD];

    const int tid = threadIdx.x;
    const int w = tid >> 5;
    const int l = tid & 31;
    const int bx = blockIdx.x;
    const int by = blockIdx.y;

    const unsigned sAb = s2u(sA);
    const unsigned sBb0 = s2u(sB[0]);
    const unsigned sBb1 = s2u(sB[1]);
    const unsigned sUb0 = s2u(sU[0]);
    const unsigned sUb1 = s2u(sU[1]);

    // ---- prologue copies (cp.async), tiles 0 and 1 ----
    {
        const char* gA = (const char*)(g_Aaug) + (size_t)bx * 128 * KAUG * 2;
        for (int k = tid; k < 640; k += THREADS) cp16(sAb + k * 16, gA + k * 16);
        const int jt0 = by * NTILES;
        const char* gB = (const char*)(g_Baug) + (size_t)jt0 * 128 * KAUG * 2;
        for (int k = tid; k < 640; k += THREADS) cp16(sBb0 + k * 16, gB + k * 16);
        const char* gU = (const char*)(g_UT) + (size_t)jt0 * CC * 256;
        for (int k = tid; k < 256; k += THREADS) {
            int row = k >> 4, q = k & 15;
            cp16(sUb0 + row * (UPAD * 2) + q * 16, gU + k * 16);
        }
        CP_COMMIT();
        const char* gB1 = (const char*)(g_Baug) + (size_t)(jt0 + 1) * 128 * KAUG * 2;
        for (int k = tid; k < 640; k += THREADS) cp16(sBb1 + k * 16, gB1 + k * 16);
        const char* gU1 = (const char*)(g_UT) + (size_t)(jt0 + 1) * CC * 256;
        for (int k = tid; k < 256; k += THREADS) {
            int row = k >> 4, q = k & 15;
            cp16(sUb1 + row * (UPAD * 2) + q * 16, gU1 + k * 16);
        }
        CP_COMMIT();
    }

    // lane address pieces
    const int lrowB = ((l >> 4) & 1) * 8 + (l & 7);
    const int lkB   = ((l >> 3) & 1) * 16;
    const int lrowA = ((l >> 3) & 1) * 8 + (l & 7);
    const int lkA   = ((l >> 4) & 1) * 16;

    const unsigned aAddr0 = sAb + (w * 16 + lrowA) * (KAUG * 2) + lkA;

    unsigned aF[2][4];
    float o[2][4];
#pragma unroll
    for (int nb = 0; nb < 2; nb++)
#pragma unroll
        for (int q = 0; q < 4; q++) o[nb][q] = 0.f;

    bool aLoaded = false;

    for (int t = 0; t < NTILES; t++) {
        if (t == NTILES - 1) asm volatile("cp.async.wait_group 0;" ::: "memory");
        else                 asm volatile("cp.async.wait_group 1;" ::: "memory");
        __syncthreads();

        if (!aLoaded) {
            ldsm4(aF[0][0], aF[0][1], aF[0][2], aF[0][3], aAddr0);
            ldsm4(aF[1][0], aF[1][1], aF[1][2], aF[1][3], aAddr0 + 32);
            aLoaded = true;
        }

        const unsigned bBase = (t & 1) ? sBb1 : sBb0;
        const unsigned uBase = (t & 1) ? sUb1 : sUb0;

        // ---- fused per-p pipeline: GEMM1(n16) -> exp -> GEMM2(k16) ----
#pragma unroll
        for (int p = 0; p < 8; p++) {
            const unsigned addrB = bBase + (p * 16 + lrowB) * (KAUG * 2) + lkB;
            unsigned b0, b1, b2, b3;
            float s0[4] = {0.f, 0.f, 0.f, 0.f};
            float s1[4] = {0.f, 0.f, 0.f, 0.f};

            ldsm4(b0, b1, b2, b3, addrB);            // k-step 0
            mma16816(s0, aF[0][0], aF[0][1], aF[0][2], aF[0][3], b0, b1);
            mma16816(s1, aF[0][0], aF[0][1], aF[0][2], aF[0][3], b2, b3);
            ldsm4(b0, b1, b2, b3, addrB + 32);       // k-step 1
            mma16816(s0, aF[1][0], aF[1][1], aF[1][2], aF[1][3], b0, b1);
            mma16816(s1, aF[1][0], aF[1][1], aF[1][2], aF[1][3], b2, b3);

            // packed f16 exp2 (W fragment == GEMM2 A fragment)
            unsigned w0 = ex2h(cvt2h(s0[1], s0[0]));
            unsigned w1 = ex2h(cvt2h(s0[3], s0[2]));
            unsigned w2 = ex2h(cvt2h(s1[1], s1[0]));
            unsigned w3 = ex2h(cvt2h(s1[3], s1[2]));

            unsigned u0, u1, u2, u3;
            ldsm4(u0, u1, u2, u3, uBase + lrowB * (UPAD * 2) + p * 32 + lkB);
            mma16816(o[0], w0, w1, w2, w3, u0, u1);
            mma16816(o[1], w0, w1, w2, w3, u2, u3);
        }

        __syncthreads();

        // ---- prefetch tile t+2 into the buffer just freed ----
        if (t + 2 < NTILES) {
            const int jt = by * NTILES + t + 2;
            const unsigned dB = (t & 1) ? sBb1 : sBb0;
            const unsigned dU = (t & 1) ? sUb1 : sUb0;
            const char* gB = (const char*)(g_Baug) + (size_t)jt * 128 * KAUG * 2;
            for (int k = tid; k < 640; k += THREADS) cp16(dB + k * 16, gB + k * 16);
            const char* gU = (const char*)(g_UT) + (size_t)jt * CC * 256;
            for (int k = tid; k < 256; k += THREADS) {
                int row = k >> 4, q = k & 15;
                cp16(dU + row * (UPAD * 2) + q * 16, gU + k * 16);
            }
            CP_COMMIT();
        } else {
            CP_COMMIT();
        }
    }

    // ---- epilogue: scatter O fragments ----
    const int g = l >> 2;
    const int tq = l & 3;
    const int i0 = bx * 128 + w * 16 + g;
#pragma unroll
    for (int nb = 0; nb < 2; nb++) {
        const int col = nb * 8 + tq * 2;
        atomicAdd(&out[i0 * CC + col],           o[nb][0]);
        atomicAdd(&out[i0 * CC + col + 1],       o[nb][1]);
        atomicAdd(&out[(i0 + 8) * CC + col],     o[nb][2]);
        atomicAdd(&out[(i0 + 8) * CC + col + 1], o[nb][3]);
    }
}

extern "C" void kernel_launch(void* const* d_in, const int* in_sizes, int n_in,
                              void* d_out, int out_size) {
    const float* U   = (const float*)d_in[0];
    const float* ref = (const float*)d_in[1];
    float* out = (float*)d_out;

    lg_pre_kernel<<<32, 256>>>(U, ref, out);

    dim3 grid(NN / 128, 16);
    lg_main_kernel<<<grid, THREADS>>>(out);
}

// round 7
// speedup vs baseline: 4.3939x; 1.0808x over previous
#include <cuda_runtime.h>
#include <cuda_fp16.h>

#define NN 8192
#define CC 16
#define KAUG 40          // halves per augmented row (24 used), 80B stride (bank-conflict-free)
#define UPAD 136
#define THREADS 256
#define NTILES 4         // j-tiles of 128 per CTA (grid.y = 16)

// ---------------- device scratch ----------------
__device__ __align__(16) __half g_Aaug[NN * KAUG];
__device__ __align__(16) __half g_Baug[NN * KAUG];
__device__ __align__(16) __half g_UT[64 * CC * 128];   // [tile][c][j]

// smem layout (in halves)
#define SA  0
#define SB0 10240
#define SB1 15360
#define SU0 20480
#define SU1 22656
#define SMEM_HALVES 24832
#define SMEM_BYTES (SMEM_HALVES * 2)

// ---------------- helpers ----------------
__device__ __forceinline__ unsigned s2u(const void* p) {
    return (unsigned)__cvta_generic_to_shared(p);
}
__device__ __forceinline__ unsigned cvt2h(float hi, float lo) {
    unsigned d; asm("cvt.rn.f16x2.f32 %0, %1, %2;" : "=r"(d) : "f"(hi), "f"(lo)); return d;
}
__device__ __forceinline__ unsigned ex2h(unsigned x) {
    unsigned y; asm("ex2.approx.f16x2 %0, %1;" : "=r"(y) : "r"(x)); return y;
}
__device__ __forceinline__ void ldsm4(unsigned& r0, unsigned& r1, unsigned& r2, unsigned& r3, unsigned a) {
    asm volatile("ldmatrix.sync.aligned.m8n8.x4.shared.b16 {%0,%1,%2,%3}, [%4];"
                 : "=r"(r0), "=r"(r1), "=r"(r2), "=r"(r3) : "r"(a));
}
__device__ __forceinline__ void mma16816(float* c, unsigned a0, unsigned a1, unsigned a2, unsigned a3,
                                         unsigned b0, unsigned b1) {
    asm volatile("mma.sync.aligned.m16n8k16.row.col.f32.f16.f16.f32 "
                 "{%0,%1,%2,%3}, {%4,%5,%6,%7}, {%8,%9}, {%0,%1,%2,%3};"
                 : "+f"(c[0]), "+f"(c[1]), "+f"(c[2]), "+f"(c[3])
                 : "r"(a0), "r"(a1), "r"(a2), "r"(a3), "r"(b0), "r"(b1));
}
__device__ __forceinline__ void cp16(unsigned saddr, const void* g) {
    asm volatile("cp.async.ca.shared.global [%0], [%1], 16;" :: "r"(saddr), "l"(g));
}
#define CP_COMMIT() asm volatile("cp.async.commit_group;" ::: "memory")

// ---------------- pre-kernel: 64 blocks x 256 threads, 128 rows each ----------------
__global__ __launch_bounds__(256) void lg_pre_kernel(const float* __restrict__ U,
                                                     const float* __restrict__ ref,
                                                     float* __restrict__ out) {
    __shared__ __half sUh[128 * 17];
    const int b = blockIdx.x;
    const int tid = threadIdx.x;

    // part 1: 128 rows of U -> out=-U, stage f16 (coalesced)
#pragma unroll
    for (int k = 0; k < 8; k++) {
        int idx = k * 256 + tid;               // 0..2047
        float f = U[b * 2048 + idx];
        out[b * 2048 + idx] = -f;
        sUh[(idx >> 4) * 17 + (idx & 15)] = __float2half_rn(f);
    }
    __syncthreads();

    // part 2: one U^T tile (16 c x 128 j) per block
    unsigned* gUTu = (unsigned*)g_UT;
#pragma unroll
    for (int k = 0; k < 4; k++) {
        int w = k * 256 + tid;                 // 0..1023 uints
        int c  = w >> 6;
        int j2 = w & 63;
        __half h0 = sUh[(2 * j2) * 17 + c];
        __half h1 = sUh[(2 * j2 + 1) * 17 + c];
        unsigned v = (unsigned)__half_as_ushort(h0) | ((unsigned)__half_as_ushort(h1) << 16);
        gUTu[((size_t)b * 16 + c) * 64 + j2] = v;
    }

    // part 3: augmented split-fp16 A/B rows (128 rows, tid<128)
    if (tid < 128) {
        const int i = b * 128 + tid;
        const float SC = 1.2011224087864498f;  // sqrt(log2 e)
        float rs[5], ss = 0.f;
#pragma unroll
        for (int k = 0; k < 5; k++) { rs[k] = ref[i * 5 + k] * SC; ss += rs[k] * rs[k]; }
        float c = -0.5f * ss;
        unsigned short rh[5], rl[5], chh, cll;
#pragma unroll
        for (int k = 0; k < 5; k++) {
            __half hh = __float2half_rn(rs[k]);
            rh[k] = __half_as_ushort(hh);
            rl[k] = __half_as_ushort(__float2half_rn(rs[k] - __half2float(hh)));
        }
        {
            __half hc = __float2half_rn(c);
            chh = __half_as_ushort(hc);
            cll = __half_as_ushort(__float2half_rn(c - __half2float(hc)));
        }
        const unsigned short ONE = 0x3C00;
        unsigned short A[KAUG], B[KAUG];
#pragma unroll
        for (int k = 0; k < KAUG; k++) { A[k] = 0; B[k] = 0; }
        // A: k0-7=[rh,ch,1,0]  k8-15=[rl,cl,0,0]  k16-23=[rh,ch,1,0]
#pragma unroll
        for (int k = 0; k < 5; k++) { A[k] = rh[k]; A[8 + k] = rl[k]; A[16 + k] = rh[k]; }
        A[5] = chh; A[6] = ONE; A[13] = cll; A[21] = chh; A[22] = ONE;
        // B: k0-7=[rh,1,ch,0]  k8-15=same  k16-23=[rl,0,cl,0]
#pragma unroll
        for (int k = 0; k < 5; k++) { B[k] = rh[k]; B[8 + k] = rh[k]; B[16 + k] = rl[k]; }
        B[5] = ONE; B[6] = chh; B[13] = ONE; B[14] = chh; B[22] = cll;
        uint4* gA = (uint4*)(g_Aaug + (size_t)i * KAUG);
        uint4* gB = (uint4*)(g_Baug + (size_t)i * KAUG);
#pragma unroll
        for (int q = 0; q < 5; q++) {
            gA[q] = ((const uint4*)A)[q];
            gB[q] = ((const uint4*)B)[q];
        }
    }
}

// ---------------- main kernel: i-tile 256 (m32 per warp) ----------------
__global__ __launch_bounds__(THREADS, 3) void lg_main_kernel(float* __restrict__ out) {
    extern __shared__ __align__(16) __half smem[];

    const int tid = threadIdx.x;
    const int w = tid >> 5;
    const int l = tid & 31;
    const int bx = blockIdx.x;
    const int by = blockIdx.y;

    const unsigned sAb = s2u(smem + SA);
    const unsigned sBb0 = s2u(smem + SB0);
    const unsigned sBb1 = s2u(smem + SB1);
    const unsigned sUb0 = s2u(smem + SU0);
    const unsigned sUb1 = s2u(smem + SU1);

    // ---- prologue copies (cp.async) ----
    {
        const char* gA = (const char*)(g_Aaug) + (size_t)bx * 256 * KAUG * 2;
        for (int k = tid; k < 1280; k += THREADS) cp16(sAb + k * 16, gA + k * 16);
        const int jt0 = by * NTILES;
        const char* gB = (const char*)(g_Baug) + (size_t)jt0 * 128 * KAUG * 2;
        for (int k = tid; k < 640; k += THREADS) cp16(sBb0 + k * 16, gB + k * 16);
        const char* gU = (const char*)(g_UT) + (size_t)jt0 * CC * 256;
        for (int k = tid; k < 256; k += THREADS) {
            int row = k >> 4, q = k & 15;
            cp16(sUb0 + row * (UPAD * 2) + q * 16, gU + k * 16);
        }
        CP_COMMIT();
        const char* gB1 = (const char*)(g_Baug) + (size_t)(jt0 + 1) * 128 * KAUG * 2;
        for (int k = tid; k < 640; k += THREADS) cp16(sBb1 + k * 16, gB1 + k * 16);
        const char* gU1 = (const char*)(g_UT) + (size_t)(jt0 + 1) * CC * 256;
        for (int k = tid; k < 256; k += THREADS) {
            int row = k >> 4, q = k & 15;
            cp16(sUb1 + row * (UPAD * 2) + q * 16, gU1 + k * 16);
        }
        CP_COMMIT();
    }

    // lane address pieces
    const int lrowB = ((l >> 4) & 1) * 8 + (l & 7);
    const int lkB   = ((l >> 3) & 1) * 16;
    const int lrowA = ((l >> 3) & 1) * 8 + (l & 7);
    const int lkA   = ((l >> 4) & 1) * 16;

    const unsigned aAddr0 = sAb + (w * 32 + lrowA) * (KAUG * 2) + lkA;       // m-block 0
    const unsigned aAddr1 = aAddr0 + 16 * (KAUG * 2);                        // m-block 1

    unsigned aF0[2][4], aF1[2][4];
    float o0[2][4], o1[2][4];
#pragma unroll
    for (int nb = 0; nb < 2; nb++)
#pragma unroll
        for (int q = 0; q < 4; q++) { o0[nb][q] = 0.f; o1[nb][q] = 0.f; }

    bool aLoaded = false;

    for (int t = 0; t < NTILES; t++) {
        if (t == NTILES - 1) asm volatile("cp.async.wait_group 0;" ::: "memory");
        else                 asm volatile("cp.async.wait_group 1;" ::: "memory");
        __syncthreads();

        if (!aLoaded) {
            ldsm4(aF0[0][0], aF0[0][1], aF0[0][2], aF0[0][3], aAddr0);
            ldsm4(aF0[1][0], aF0[1][1], aF0[1][2], aF0[1][3], aAddr0 + 32);
            ldsm4(aF1[0][0], aF1[0][1], aF1[0][2], aF1[0][3], aAddr1);
            ldsm4(aF1[1][0], aF1[1][1], aF1[1][2], aF1[1][3], aAddr1 + 32);
            aLoaded = true;
        }

        const unsigned bBase = (t & 1) ? sBb1 : sBb0;
        const unsigned uBase = (t & 1) ? sUb1 : sUb0;

#pragma unroll
        for (int p = 0; p < 8; p++) {
            const unsigned addrB = bBase + (p * 16 + lrowB) * (KAUG * 2) + lkB;
            unsigned b0, b1, b2, b3, b4, b5, b6, b7;
            ldsm4(b0, b1, b2, b3, addrB);        // k-step 0
            ldsm4(b4, b5, b6, b7, addrB + 32);   // k-step 1

            // m-block 0: S -> exp -> W fragment
            unsigned w00, w01, w02, w03;
            {
                float s0[4] = {0.f, 0.f, 0.f, 0.f};
                float s1[4] = {0.f, 0.f, 0.f, 0.f};
                mma16816(s0, aF0[0][0], aF0[0][1], aF0[0][2], aF0[0][3], b0, b1);
                mma16816(s1, aF0[0][0], aF0[0][1], aF0[0][2], aF0[0][3], b2, b3);
                mma16816(s0, aF0[1][0], aF0[1][1], aF0[1][2], aF0[1][3], b4, b5);
                mma16816(s1, aF0[1][0], aF0[1][1], aF0[1][2], aF0[1][3], b6, b7);
                w00 = ex2h(cvt2h(s0[1], s0[0]));
                w01 = ex2h(cvt2h(s0[3], s0[2]));
                w02 = ex2h(cvt2h(s1[1], s1[0]));
                w03 = ex2h(cvt2h(s1[3], s1[2]));
            }
            // m-block 1
            unsigned w10, w11, w12, w13;
            {
                float s0[4] = {0.f, 0.f, 0.f, 0.f};
                float s1[4] = {0.f, 0.f, 0.f, 0.f};
                mma16816(s0, aF1[0][0], aF1[0][1], aF1[0][2], aF1[0][3], b0, b1);
                mma16816(s1, aF1[0][0], aF1[0][1], aF1[0][2], aF1[0][3], b2, b3);
                mma16816(s0, aF1[1][0], aF1[1][1], aF1[1][2], aF1[1][3], b4, b5);
                mma16816(s1, aF1[1][0], aF1[1][1], aF1[1][2], aF1[1][3], b6, b7);
                w10 = ex2h(cvt2h(s0[1], s0[0]));
                w11 = ex2h(cvt2h(s0[3], s0[2]));
                w12 = ex2h(cvt2h(s1[1], s1[0]));
                w13 = ex2h(cvt2h(s1[3], s1[2]));
            }

            unsigned u0, u1, u2, u3;
            ldsm4(u0, u1, u2, u3, uBase + lrowB * (UPAD * 2) + p * 32 + lkB);
            mma16816(o0[0], w00, w01, w02, w03, u0, u1);
            mma16816(o0[1], w00, w01, w02, w03, u2, u3);
            mma16816(o1[0], w10, w11, w12, w13, u0, u1);
            mma16816(o1[1], w10, w11, w12, w13, u2, u3);
        }

        __syncthreads();

        // ---- prefetch tile t+2 ----
        if (t + 2 < NTILES) {
            const int jt = by * NTILES + t + 2;
            const unsigned dB = (t & 1) ? sBb1 : sBb0;
            const unsigned dU = (t & 1) ? sUb1 : sUb0;
            const char* gB = (const char*)(g_Baug) + (size_t)jt * 128 * KAUG * 2;
            for (int k = tid; k < 640; k += THREADS) cp16(dB + k * 16, gB + k * 16);
            const char* gU = (const char*)(g_UT) + (size_t)jt * CC * 256;
            for (int k = tid; k < 256; k += THREADS) {
                int row = k >> 4, q = k & 15;
                cp16(dU + row * (UPAD * 2) + q * 16, gU + k * 16);
            }
            CP_COMMIT();
        } else {
            CP_COMMIT();
        }
    }

    // ---- epilogue ----
    const int g = l >> 2;
    const int tq = l & 3;
    const int i0 = bx * 256 + w * 32 + g;
#pragma unroll
    for (int nb = 0; nb < 2; nb++) {
        const int col = nb * 8 + tq * 2;
        atomicAdd(&out[i0 * CC + col],            o0[nb][0]);
        atomicAdd(&out[i0 * CC + col + 1],        o0[nb][1]);
        atomicAdd(&out[(i0 + 8) * CC + col],      o0[nb][2]);
        atomicAdd(&out[(i0 + 8) * CC + col + 1],  o0[nb][3]);
        atomicAdd(&out[(i0 + 16) * CC + col],     o1[nb][0]);
        atomicAdd(&out[(i0 + 16) * CC + col + 1], o1[nb][1]);
        atomicAdd(&out[(i0 + 24) * CC + col],     o1[nb][2]);
        atomicAdd(&out[(i0 + 24) * CC + col + 1], o1[nb][3]);
    }
}

extern "C" void kernel_launch(void* const* d_in, const int* in_sizes, int n_in,
                              void* d_out, int out_size) {
    const float* U   = (const float*)d_in[0];
    const float* ref = (const float*)d_in[1];
    float* out = (float*)d_out;

    static int attrSet = 0;
    if (!attrSet) {
        cudaFuncSetAttribute(lg_main_kernel, cudaFuncAttributeMaxDynamicSharedMemorySize, SMEM_BYTES);
        attrSet = 1;
    }

    lg_pre_kernel<<<64, 256>>>(U, ref, out);

    dim3 grid(NN / 256, 16);
    lg_main_kernel<<<grid, THREADS, SMEM_BYTES>>>(out);
}